// round 14
// baseline (speedup 1.0000x reference)
#include <cuda_runtime.h>
#include <cuda_bf16.h>
#include <cuda_fp16.h>
#include <math.h>
#include <stdint.h>

// Problem constants
#define B_   4
#define T_   2048
#define D_   1024
#define H_   16
#define HD_  64
#define NTOK (B_ * T_)   // 8192
#define BH_  (B_ * H_)   // 64

// ---------------------------------------------------------------------------
// Scratch (device globals: allocation-free rule)
// ---------------------------------------------------------------------------
__device__ float g_cos[T_ * 32];
__device__ float g_sin[T_ * 32];
__device__ float g_freqf[16];

// fp16 x split (projections); later reused as fp16 attn-out split (wo GEMM)
__device__ __half g_axh[NTOK * D_];
__device__ __half g_axl[NTOK * D_];
// all 4 weights fp16 single
__device__ __half g_w16[4][D_ * D_];

// head-major fp16 for flash: Q hi/lo (exact), K single, V single  [bh][T][HD]
__device__ __half g_q16h[BH_ * T_ * HD_];
__device__ __half g_q16l[BH_ * T_ * HD_];
__device__ __half g_k16[BH_ * T_ * HD_];
__device__ __half g_v16[BH_ * T_ * HD_];

#define QSCALE (0.125f * 1.4426950408889634f)

// ---------------------------------------------------------------------------
// PTX helpers (base compute_103 target: mma.sync / ldmatrix / cp.async only)
// ---------------------------------------------------------------------------
__device__ __forceinline__ uint32_t smem_to_u32(const void* p) {
    uint32_t a;
    asm("{ .reg .u64 t; cvta.to.shared.u64 t, %1; cvt.u32.u64 %0, t; }"
        : "=r"(a) : "l"(p));
    return a;
}

__device__ __forceinline__ void ldsm_x4(uint32_t* r, uint32_t addr) {
    asm volatile("ldmatrix.sync.aligned.m8n8.x4.shared.b16 {%0,%1,%2,%3}, [%4];"
                 : "=r"(r[0]), "=r"(r[1]), "=r"(r[2]), "=r"(r[3]) : "r"(addr));
}

__device__ __forceinline__ void ldsm_x4_t(uint32_t* r, uint32_t addr) {
    asm volatile("ldmatrix.sync.aligned.m8n8.x4.trans.shared.b16 {%0,%1,%2,%3}, [%4];"
                 : "=r"(r[0]), "=r"(r[1]), "=r"(r[2]), "=r"(r[3]) : "r"(addr));
}

__device__ __forceinline__ void mma_f16(float* c, const uint32_t* a, const uint32_t* b) {
    asm volatile(
        "mma.sync.aligned.m16n8k16.row.col.f32.f16.f16.f32 "
        "{%0,%1,%2,%3}, {%4,%5,%6,%7}, {%8,%9}, {%0,%1,%2,%3};"
        : "+f"(c[0]), "+f"(c[1]), "+f"(c[2]), "+f"(c[3])
        : "r"(a[0]), "r"(a[1]), "r"(a[2]), "r"(a[3]), "r"(b[0]), "r"(b[1]));
}

__device__ __forceinline__ void cp_async16(uint32_t dst, const void* src) {
    asm volatile("cp.async.cg.shared.global [%0], [%1], 16;"
                 :: "r"(dst), "l"(src));
}
__device__ __forceinline__ void cp_commit() {
    asm volatile("cp.async.commit_group;" ::: "memory");
}
template <int N>
__device__ __forceinline__ void cp_wait() {
    asm volatile("cp.async.wait_group %0;" :: "n"(N) : "memory");
}

__device__ __forceinline__ uint32_t pack_half2(__half a, __half b) {
    __half2 h = __halves2half2(a, b);
    return *reinterpret_cast<uint32_t*>(&h);
}

// ---------------------------------------------------------------------------
// x split: fp16 hi/lo (near-exact representation of fp32 x)
// ---------------------------------------------------------------------------
__global__ __launch_bounds__(256) void split_x_kernel(const float* __restrict__ src) {
    int i4 = (blockIdx.x * blockDim.x + threadIdx.x) * 4;
    if (i4 >= NTOK * D_) return;
    float4 v = *(const float4*)(src + i4);
    __half h0 = __float2half_rn(v.x), h1 = __float2half_rn(v.y);
    __half h2 = __float2half_rn(v.z), h3 = __float2half_rn(v.w);
    reinterpret_cast<__half2*>(g_axh + i4)[0] = __halves2half2(h0, h1);
    reinterpret_cast<__half2*>(g_axh + i4)[1] = __halves2half2(h2, h3);
    reinterpret_cast<__half2*>(g_axl + i4)[0] = __halves2half2(
        __float2half_rn(v.x - __half2float(h0)),
        __float2half_rn(v.y - __half2float(h1)));
    reinterpret_cast<__half2*>(g_axl + i4)[1] = __halves2half2(
        __float2half_rn(v.z - __half2float(h2)),
        __float2half_rn(v.w - __half2float(h3)));
}

// all 4 weights -> fp16 single
__global__ __launch_bounds__(256) void split_w_kernel(
    const float* __restrict__ w0, const float* __restrict__ w1,
    const float* __restrict__ w2, const float* __restrict__ w3)
{
    int i4 = (blockIdx.x * blockDim.x + threadIdx.x) * 4;
    if (i4 >= 4 * D_ * D_) return;
    int wi = i4 >> 20;
    int off = i4 & (D_ * D_ - 1);
    const float* src = (wi == 0) ? w0 : (wi == 1) ? w1 : (wi == 2) ? w2 : w3;
    float4 v = *(const float4*)(src + off);
    reinterpret_cast<__half2*>(g_w16[wi] + off)[0] =
        __halves2half2(__float2half_rn(v.x), __float2half_rn(v.y));
    reinterpret_cast<__half2*>(g_w16[wi] + off)[1] =
        __halves2half2(__float2half_rn(v.z), __float2half_rn(v.w));
}

// ---------------------------------------------------------------------------
// RoPE tables
// ---------------------------------------------------------------------------
__global__ void rope_freq_kernel() {
    int j = threadIdx.x;
    if (j < 16) g_freqf[j] = (float)pow(1.0 / 1024.0, (double)j / 15.0);
}

__global__ __launch_bounds__(256) void rope_tables_kernel() {
    int i = blockIdx.x * blockDim.x + threadIdx.x;
    if (i >= T_ * 32) return;
    int t = i >> 5;
    int j = i & 31;
    if (j >= 16) { g_cos[i] = 1.0f; g_sin[i] = 0.0f; return; }
    float theta = (float)t * g_freqf[j];
    const float inv2pi = 0.15915494309189535f;
    const float c1 = 6.28125f;
    const float c2 = 1.9345283508300781e-3f;
    const float c3 = 7.7882876e-7f;
    float n = rintf(theta * inv2pi);
    float r = fmaf(-n, c1, theta);
    r = fmaf(-n, c2, r);
    r = fmaf(-n, c3, r);
    g_cos[i] = cosf(r);
    g_sin[i] = sinf(r);
}

// ---------------------------------------------------------------------------
// Unified fp16 2-pass GEMM (AhBh + AlBh): CTA 256x128, 8 warps of 64x64,
// BK=64, 2-stage ring, 144B rows. mode = wbase + z:
//   0: Q -> norm+rope -> head-major fp16 hi/lo
//   1: K -> norm+rope -> head-major fp16 single
//   2: V -> head-major fp16 single
//   3: wo -> fp32 out
// ---------------------------------------------------------------------------
#define GF_ROWB   144u
#define GF_A_ARR  (256 * 144)
#define GF_B_ARR  (128 * 144)
#define GF_STAGE  (2 * GF_A_ARR + GF_B_ARR)   // 92160
#define GF_SMEM   (2 * GF_STAGE)              // 184320
#define GF_CHUNKS 16

__device__ __forceinline__ void gf_load_stage(
    uint32_t sbase, const __half* a_hi, const __half* a_lo,
    const __half* bh, int k0, int tid)
{
    int seg = tid & 7;
    int r0  = tid >> 3;
    const __half* ah = a_hi + k0 + seg * 8;
    const __half* al = a_lo + k0 + seg * 8;
    const __half* bb = bh + k0 + seg * 8;
    uint32_t d0 = sbase + seg * 16;
#pragma unroll
    for (int rr = 0; rr < 8; rr++) {
        int row = r0 + rr * 32;
        cp_async16(d0 + row * GF_ROWB, ah + (size_t)row * D_);
        cp_async16(d0 + GF_A_ARR + row * GF_ROWB, al + (size_t)row * D_);
    }
#pragma unroll
    for (int rr = 0; rr < 4; rr++) {
        int row = r0 + rr * 32;
        cp_async16(d0 + 2 * GF_A_ARR + row * GF_ROWB, bb + (size_t)row * D_);
    }
}

__global__ __launch_bounds__(256, 1) void gemm_f16_kernel(
    const __half* __restrict__ Ahi, const __half* __restrict__ Alo,
    int wbase, float* Cout)
{
    extern __shared__ __align__(128) char smem[];
    uint32_t sb = smem_to_u32(smem);

    const int tid  = threadIdx.x;
    const int wid  = tid >> 5;
    const int lane = tid & 31;
    const int wm = wid & 3;
    const int wn = wid >> 2;
    const int bm = blockIdx.y * 256;
    const int bn = blockIdx.x * 128;
    const int mode = wbase + blockIdx.z;

    const __half* a_hi = Ahi + (size_t)bm * D_;
    const __half* a_lo = Alo + (size_t)bm * D_;
    const __half* b_hi = g_w16[mode] + (size_t)bn * D_;

    float c[4][8][4];
#pragma unroll
    for (int mt = 0; mt < 4; mt++)
#pragma unroll
        for (int nt = 0; nt < 8; nt++)
#pragma unroll
            for (int r = 0; r < 4; r++) c[mt][nt][r] = 0.0f;

    const int rowA = lane & 15;
    const int kbA  = lane >> 4;
    const int rowB = (lane & 7) + ((lane >> 4) << 3);
    const int kbB  = (lane >> 3) & 1;
    const uint32_t aoff = (uint32_t)(wm * 64 + rowA) * GF_ROWB + kbA * 16;
    const uint32_t boff = (uint32_t)(wn * 64 + rowB) * GF_ROWB + kbB * 16;

    gf_load_stage(sb, a_hi, a_lo, b_hi, 0, tid);
    cp_commit();

    for (int i = 0; i < GF_CHUNKS; i++) {
        if (i + 1 < GF_CHUNKS) {
            gf_load_stage(sb + ((i + 1) & 1) * GF_STAGE, a_hi, a_lo, b_hi,
                          (i + 1) * 64, tid);
            cp_commit();
            cp_wait<1>();
        } else {
            cp_wait<0>();
        }
        __syncthreads();

        uint32_t st = sb + (i & 1) * GF_STAGE;
#pragma unroll
        for (int ks = 0; ks < 4; ks++) {
            uint32_t koff = ks * 32;
            uint32_t fah[4][4], fal[4][4], fbh[4][4];
#pragma unroll
            for (int mt = 0; mt < 4; mt++) {
                ldsm_x4(fah[mt], st + aoff + koff + mt * 16 * GF_ROWB);
                ldsm_x4(fal[mt], st + GF_A_ARR + aoff + koff + mt * 16 * GF_ROWB);
            }
#pragma unroll
            for (int np = 0; np < 4; np++)
                ldsm_x4(fbh[np], st + 2 * GF_A_ARR + boff + koff + np * 16 * GF_ROWB);
#pragma unroll
            for (int np = 0; np < 4; np++)
#pragma unroll
                for (int mt = 0; mt < 4; mt++) {
                    mma_f16(c[mt][np * 2 + 0], fah[mt], fbh[np] + 0);
                    mma_f16(c[mt][np * 2 + 1], fah[mt], fbh[np] + 2);
                }
#pragma unroll
            for (int np = 0; np < 4; np++)
#pragma unroll
                for (int mt = 0; mt < 4; mt++) {
                    mma_f16(c[mt][np * 2 + 0], fal[mt], fbh[np] + 0);
                    mma_f16(c[mt][np * 2 + 1], fal[mt], fbh[np] + 2);
                }
        }
        __syncthreads();
    }

    const int erow = bm + wm * 64 + (lane >> 2);
    const int ecol = bn + wn * 64 + (lane & 3) * 2;

    if (mode == 3) {
        // wo: fp32 out
#pragma unroll
        for (int mt = 0; mt < 4; mt++)
#pragma unroll
            for (int nt = 0; nt < 8; nt++) {
                int r0 = erow + mt * 16;
                int cc = ecol + (nt >> 1) * 16 + (nt & 1) * 8;
                *(float2*)&Cout[(size_t)r0 * D_ + cc]       = make_float2(c[mt][nt][0], c[mt][nt][1]);
                *(float2*)&Cout[(size_t)(r0 + 8) * D_ + cc] = make_float2(c[mt][nt][2], c[mt][nt][3]);
            }
    } else if (mode == 2) {
        // V: head-major fp16 single
#pragma unroll
        for (int mt = 0; mt < 4; mt++)
#pragma unroll
            for (int nt = 0; nt < 8; nt++) {
                int cc = ecol + (nt >> 1) * 16 + (nt & 1) * 8;
                int h = cc >> 6, hd = cc & 63;
#pragma unroll
                for (int rh = 0; rh < 2; rh++) {
                    int token = erow + mt * 16 + rh * 8;
                    int b = token >> 11, t = token & (T_ - 1);
                    size_t oi = (((size_t)(b * H_ + h)) * T_ + t) * HD_ + hd;
                    *reinterpret_cast<__half2*>(g_v16 + oi) = __halves2half2(
                        __float2half_rn(c[mt][nt][rh * 2]),
                        __float2half_rn(c[mt][nt][rh * 2 + 1]));
                }
            }
    } else {
        // Q (0) / K (1): fused RMSNorm + RoPE, head-major fp16
        const float scale = (mode == 0) ? QSCALE : 1.0f;
        const int h = (bn >> 6) + wn;
        const int jbase = (lane & 3) * 2;
#pragma unroll
        for (int mt = 0; mt < 4; mt++) {
#pragma unroll
            for (int rh = 0; rh < 2; rh++) {
                int token = erow + mt * 16 + rh * 8;
                int b = token >> 11, t = token & (T_ - 1);
                float ss = 0.0f;
#pragma unroll
                for (int nt = 0; nt < 8; nt++) {
                    float v0 = c[mt][nt][rh * 2], v1 = c[mt][nt][rh * 2 + 1];
                    ss = fmaf(v0, v0, ss);
                    ss = fmaf(v1, v1, ss);
                }
                ss += __shfl_xor_sync(0xffffffffu, ss, 1);
                ss += __shfl_xor_sync(0xffffffffu, ss, 2);
                float rn = rsqrtf(ss * (1.0f / 64.0f) + 1e-6f) * scale;
                size_t ob = (((size_t)(b * H_ + h)) * T_ + t) * HD_;
                const float* ct = g_cos + t * 32;
                const float* stb = g_sin + t * 32;
#pragma unroll
                for (int nt = 0; nt < 4; nt++) {
                    int j0 = jbase + (nt >> 1) * 16 + (nt & 1) * 8;
                    float x1a = c[mt][nt][rh * 2]     * rn;
                    float x1b = c[mt][nt][rh * 2 + 1] * rn;
                    float x2a = c[mt][nt + 4][rh * 2]     * rn;
                    float x2b = c[mt][nt + 4][rh * 2 + 1] * rn;
                    float ca = ct[j0],     sa = stb[j0];
                    float cb = ct[j0 + 1], sb2 = stb[j0 + 1];
                    float y1a = x1a * ca + x2a * sa;
                    float y2a = -x1a * sa + x2a * ca;
                    float y1b = x1b * cb + x2b * sb2;
                    float y2b = -x1b * sb2 + x2b * cb;
                    if (mode == 0) {
                        __half h1a = __float2half_rn(y1a), h1b = __float2half_rn(y1b);
                        __half h2a = __float2half_rn(y2a), h2b = __float2half_rn(y2b);
                        *reinterpret_cast<__half2*>(g_q16h + ob + j0)      = __halves2half2(h1a, h1b);
                        *reinterpret_cast<__half2*>(g_q16h + ob + j0 + 32) = __halves2half2(h2a, h2b);
                        *reinterpret_cast<__half2*>(g_q16l + ob + j0) = __halves2half2(
                            __float2half_rn(y1a - __half2float(h1a)),
                            __float2half_rn(y1b - __half2float(h1b)));
                        *reinterpret_cast<__half2*>(g_q16l + ob + j0 + 32) = __halves2half2(
                            __float2half_rn(y2a - __half2float(h2a)),
                            __float2half_rn(y2b - __half2float(h2b)));
                    } else {
                        *reinterpret_cast<__half2*>(g_k16 + ob + j0) = __halves2half2(
                            __float2half_rn(y1a), __float2half_rn(y1b));
                        *reinterpret_cast<__half2*>(g_k16 + ob + j0 + 32) = __halves2half2(
                            __float2half_rn(y2a), __float2half_rn(y2b));
                    }
                }
            }
        }
    }
}

// ---------------------------------------------------------------------------
// Flash attention, all fp16: S = (Qh+Ql) x K16 (2 passes), PV = (Ph+Pl) x V16.
// KV stage: K16, V16 (2 arrays). exp2 softmax.
// Epilogue writes fp16 hi/lo attn-out (token-major) for the wo GEMM.
// ---------------------------------------------------------------------------
#define FROWB   144u
#define FQ_SIZE (128 * 144)
#define FKV_OFF (2 * FQ_SIZE)
#define FKV_ARR (128 * 144)
#define FSTAGE  (2 * FKV_ARR)              // 36864
#define FMMA_SMEM (FKV_OFF + 2 * FSTAGE)   // 110592

__device__ __forceinline__ void f_load_kv(
    uint32_t dst, const __half* kh, const __half* vh, size_t goff, int tid)
{
    int seg = tid & 7, r0 = tid >> 3;
    const __half* s0 = kh + goff + seg * 8;
    const __half* s1 = vh + goff + seg * 8;
    uint32_t d = dst + seg * 16;
#pragma unroll
    for (int rr = 0; rr < 4; rr++) {
        int row = r0 + rr * 32;
        cp_async16(d + row * FROWB, s0 + row * HD_);
        cp_async16(d + FKV_ARR + row * FROWB, s1 + row * HD_);
    }
}

__global__ __launch_bounds__(256, 1) void flash_mma_kernel(
    __half* __restrict__ Ohi, __half* __restrict__ Olo)
{
    extern __shared__ __align__(128) char fsm[];
    uint32_t sb = smem_to_u32(fsm);
    const int tid = threadIdx.x, wid = tid >> 5, lane = tid & 31;
    const int bh = blockIdx.x;
    const int qt = 15 - blockIdx.y;
    const int b = bh >> 4, h = bh & 15;
    const size_t headoff = (size_t)bh * T_ * HD_;
    const int nkt = qt + 1;

    {
        int seg = tid & 7, r0 = tid >> 3;
        const __half* q0 = g_q16h + headoff + (size_t)qt * 128 * HD_ + seg * 8;
        const __half* q1 = g_q16l + headoff + (size_t)qt * 128 * HD_ + seg * 8;
#pragma unroll
        for (int rr = 0; rr < 4; rr++) {
            int row = r0 + rr * 32;
            cp_async16(sb + row * FROWB + seg * 16, q0 + row * HD_);
            cp_async16(sb + FQ_SIZE + row * FROWB + seg * 16, q1 + row * HD_);
        }
    }
    f_load_kv(sb + FKV_OFF, g_k16, g_v16, headoff, tid);
    cp_commit();

    uint32_t fqh[4][4], fql[4][4];
    float o[8][4];
#pragma unroll
    for (int nt = 0; nt < 8; nt++)
#pragma unroll
        for (int r = 0; r < 4; r++) o[nt][r] = 0.0f;
    float m0 = -1e30f, m1 = -1e30f, l0 = 0.0f, l1 = 0.0f;

    const uint32_t qrow_off = (uint32_t)(wid * 16 + (lane & 15)) * FROWB + (lane >> 4) * 16;
    const uint32_t krow_off = (uint32_t)((lane & 7) + ((lane >> 4) << 3)) * FROWB
                              + ((lane >> 3) & 1) * 16;
    const uint32_t vrow_off = (uint32_t)(lane & 15) * FROWB + (lane >> 4) * 16;

    for (int jt = 0; jt < nkt; jt++) {
        if (jt + 1 < nkt) {
            f_load_kv(sb + FKV_OFF + ((jt + 1) & 1) * FSTAGE, g_k16, g_v16,
                      headoff + (size_t)(jt + 1) * 128 * HD_, tid);
            cp_commit();
            cp_wait<1>();
        } else {
            cp_wait<0>();
        }
        __syncthreads();

        if (jt == 0) {
#pragma unroll
            for (int ks = 0; ks < 4; ks++) {
                ldsm_x4(fqh[ks], sb + qrow_off + ks * 32);
                ldsm_x4(fql[ks], sb + FQ_SIZE + qrow_off + ks * 32);
            }
        }

        uint32_t st = sb + FKV_OFF + (jt & 1) * FSTAGE;

        float s[16][4];
#pragma unroll
        for (int nt = 0; nt < 16; nt++)
#pragma unroll
            for (int r = 0; r < 4; r++) s[nt][r] = 0.0f;

#pragma unroll
        for (int np = 0; np < 8; np++) {
#pragma unroll
            for (int ks = 0; ks < 4; ks++) {
                uint32_t addr = st + krow_off + np * 16 * FROWB + ks * 32;
                uint32_t fk[4];
                ldsm_x4(fk, addr);
                mma_f16(s[2 * np],     fqh[ks], fk + 0);
                mma_f16(s[2 * np + 1], fqh[ks], fk + 2);
                mma_f16(s[2 * np],     fql[ks], fk + 0);
                mma_f16(s[2 * np + 1], fql[ks], fk + 2);
            }
        }

        if (jt == qt) {
            int grow = qt * 128 + wid * 16 + (lane >> 2);
            int gc0 = jt * 128 + (lane & 3) * 2;
#pragma unroll
            for (int nt = 0; nt < 16; nt++) {
                int cc = gc0 + nt * 8;
                if (cc > grow)          s[nt][0] = -1e30f;
                if (cc + 1 > grow)      s[nt][1] = -1e30f;
                if (cc > grow + 8)      s[nt][2] = -1e30f;
                if (cc + 1 > grow + 8)  s[nt][3] = -1e30f;
            }
        }

        float mx0 = -1e30f, mx1 = -1e30f;
#pragma unroll
        for (int nt = 0; nt < 16; nt++) {
            mx0 = fmaxf(mx0, fmaxf(s[nt][0], s[nt][1]));
            mx1 = fmaxf(mx1, fmaxf(s[nt][2], s[nt][3]));
        }
        mx0 = fmaxf(mx0, __shfl_xor_sync(0xffffffffu, mx0, 1));
        mx0 = fmaxf(mx0, __shfl_xor_sync(0xffffffffu, mx0, 2));
        mx1 = fmaxf(mx1, __shfl_xor_sync(0xffffffffu, mx1, 1));
        mx1 = fmaxf(mx1, __shfl_xor_sync(0xffffffffu, mx1, 2));
        float mn0 = fmaxf(m0, mx0), mn1 = fmaxf(m1, mx1);
        float al0 = exp2f(m0 - mn0), al1 = exp2f(m1 - mn1);
        float rs0 = 0.0f, rs1 = 0.0f;
#pragma unroll
        for (int nt = 0; nt < 16; nt++) {
            s[nt][0] = exp2f(s[nt][0] - mn0);
            s[nt][1] = exp2f(s[nt][1] - mn0);
            s[nt][2] = exp2f(s[nt][2] - mn1);
            s[nt][3] = exp2f(s[nt][3] - mn1);
            rs0 += s[nt][0] + s[nt][1];
            rs1 += s[nt][2] + s[nt][3];
        }
        rs0 += __shfl_xor_sync(0xffffffffu, rs0, 1);
        rs0 += __shfl_xor_sync(0xffffffffu, rs0, 2);
        rs1 += __shfl_xor_sync(0xffffffffu, rs1, 1);
        rs1 += __shfl_xor_sync(0xffffffffu, rs1, 2);
        l0 = l0 * al0 + rs0; m0 = mn0;
        l1 = l1 * al1 + rs1; m1 = mn1;
#pragma unroll
        for (int nt = 0; nt < 8; nt++) {
            o[nt][0] *= al0; o[nt][1] *= al0;
            o[nt][2] *= al1; o[nt][3] *= al1;
        }

        // P -> fp16 hi/lo A-fragments
        uint32_t fph[8][4], fpl[8][4];
#pragma unroll
        for (int f = 0; f < 8; f++) {
#pragma unroll
            for (int half = 0; half < 2; half++) {
                int nt = 2 * f + half;
#pragma unroll
                for (int rh = 0; rh < 2; rh++) {
                    float p0 = s[nt][rh * 2], p1 = s[nt][rh * 2 + 1];
                    __half h0 = __float2half_rn(p0), h1 = __float2half_rn(p1);
                    fph[f][half * 2 + rh] = pack_half2(h0, h1);
                    fpl[f][half * 2 + rh] = pack_half2(
                        __float2half_rn(p0 - __half2float(h0)),
                        __float2half_rn(p1 - __half2float(h1)));
                }
            }
        }

        // O += P V (fp16 2-pass)
#pragma unroll
        for (int nh = 0; nh < 4; nh++) {
#pragma unroll
            for (int ks = 0; ks < 8; ks++) {
                uint32_t addr = st + FKV_ARR + vrow_off + ks * 16 * FROWB + nh * 32;
                uint32_t fv[4];
                ldsm_x4_t(fv, addr);
                mma_f16(o[2 * nh],     fph[ks], fv + 0);
                mma_f16(o[2 * nh + 1], fph[ks], fv + 2);
                mma_f16(o[2 * nh],     fpl[ks], fv + 0);
                mma_f16(o[2 * nh + 1], fpl[ks], fv + 2);
            }
        }
        __syncthreads();
    }

    // epilogue: normalize + fp16 hi/lo split, token-major [b][t][h*64+hd]
    float inv0 = 1.0f / l0, inv1 = 1.0f / l1;
    int row = qt * 128 + wid * 16 + (lane >> 2);
    size_t base0 = ((size_t)b * T_ + row) * D_ + h * 64 + (lane & 3) * 2;
    size_t base1 = base0 + (size_t)8 * D_;
#pragma unroll
    for (int nt = 0; nt < 8; nt++) {
        float v0 = o[nt][0] * inv0, v1 = o[nt][1] * inv0;
        float v2 = o[nt][2] * inv1, v3 = o[nt][3] * inv1;
        __half h0 = __float2half_rn(v0), h1 = __float2half_rn(v1);
        __half h2 = __float2half_rn(v2), h3 = __float2half_rn(v3);
        *reinterpret_cast<__half2*>(Ohi + base0 + nt * 8) = __halves2half2(h0, h1);
        *reinterpret_cast<__half2*>(Ohi + base1 + nt * 8) = __halves2half2(h2, h3);
        *reinterpret_cast<__half2*>(Olo + base0 + nt * 8) = __halves2half2(
            __float2half_rn(v0 - __half2float(h0)),
            __float2half_rn(v1 - __half2float(h1)));
        *reinterpret_cast<__half2*>(Olo + base1 + nt * 8) = __halves2half2(
            __float2half_rn(v2 - __half2float(h2)),
            __float2half_rn(v3 - __half2float(h3)));
    }
}

// ---------------------------------------------------------------------------
// Launch
// ---------------------------------------------------------------------------
extern "C" void kernel_launch(void* const* d_in, const int* in_sizes, int n_in,
                              void* d_out, int out_size)
{
    (void)in_sizes; (void)n_in; (void)out_size;
    const float* x  = (const float*)d_in[0];
    const float* w[4] = {(const float*)d_in[1], (const float*)d_in[2],
                         (const float*)d_in[3], (const float*)d_in[4]};
    float* out = (float*)d_out;

    __half *axh, *axl;
    cudaGetSymbolAddress((void**)&axh, g_axh);
    cudaGetSymbolAddress((void**)&axl, g_axl);

    cudaFuncSetAttribute(gemm_f16_kernel,
                         cudaFuncAttributeMaxDynamicSharedMemorySize, GF_SMEM);
    cudaFuncSetAttribute(flash_mma_kernel,
                         cudaFuncAttributeMaxDynamicSharedMemorySize, FMMA_SMEM);

    rope_freq_kernel<<<1, 16>>>();
    rope_tables_kernel<<<(T_ * 32 + 255) / 256, 256>>>();

    split_x_kernel<<<(NTOK * D_ / 4 + 255) / 256, 256>>>(x);
    split_w_kernel<<<(4 * D_ * D_ / 4 + 255) / 256, 256>>>(w[0], w[1], w[2], w[3]);

    // Q/K/V projections fused in one launch (z = 0,1,2)
    gemm_f16_kernel<<<dim3(D_ / 128, NTOK / 256, 3), 256, GF_SMEM>>>(
        axh, axl, 0, out);

    // flash: writes fp16 hi/lo attn-out into axh/axl
    flash_mma_kernel<<<dim3(BH_, T_ / 128), 256, FMMA_SMEM>>>(axh, axl);

    // wo projection -> fp32 out
    gemm_f16_kernel<<<dim3(D_ / 128, NTOK / 256, 1), 256, GF_SMEM>>>(
        axh, axl, 3, out);
}

// round 16
// speedup vs baseline: 1.4220x; 1.4220x over previous
#include <cuda_runtime.h>
#include <cuda_bf16.h>
#include <cuda_fp16.h>
#include <math.h>
#include <stdint.h>

// Problem constants
#define B_   4
#define T_   2048
#define D_   1024
#define H_   16
#define HD_  64
#define NTOK (B_ * T_)   // 8192
#define BH_  (B_ * H_)   // 64

// ---------------------------------------------------------------------------
// Scratch (device globals: allocation-free rule)
// ---------------------------------------------------------------------------
__device__ float g_cos[T_ * 32];
__device__ float g_sin[T_ * 32];
__device__ float g_freqf[16];

// fp16 x split (projections); later reused as fp16 attn-out split (wo GEMM)
__device__ __half g_axh[NTOK * D_];
__device__ __half g_axl[NTOK * D_];
// all 4 weights fp16 single
__device__ __half g_w16[4][D_ * D_];

// head-major for flash: Q/K bf16 hi/lo, V fp16 single  [bh][T][HD]
__device__ __nv_bfloat16 g_qhi[BH_ * T_ * HD_];
__device__ __nv_bfloat16 g_qlo[BH_ * T_ * HD_];
__device__ __nv_bfloat16 g_khi[BH_ * T_ * HD_];
__device__ __nv_bfloat16 g_klo[BH_ * T_ * HD_];
__device__ __half g_v16[BH_ * T_ * HD_];

#define QSCALE (0.125f * 1.4426950408889634f)

// ---------------------------------------------------------------------------
// PTX helpers (base compute_103 target: mma.sync / ldmatrix / cp.async only)
// ---------------------------------------------------------------------------
__device__ __forceinline__ uint32_t smem_to_u32(const void* p) {
    uint32_t a;
    asm("{ .reg .u64 t; cvta.to.shared.u64 t, %1; cvt.u32.u64 %0, t; }"
        : "=r"(a) : "l"(p));
    return a;
}

__device__ __forceinline__ void ldsm_x4(uint32_t* r, uint32_t addr) {
    asm volatile("ldmatrix.sync.aligned.m8n8.x4.shared.b16 {%0,%1,%2,%3}, [%4];"
                 : "=r"(r[0]), "=r"(r[1]), "=r"(r[2]), "=r"(r[3]) : "r"(addr));
}

__device__ __forceinline__ void ldsm_x4_t(uint32_t* r, uint32_t addr) {
    asm volatile("ldmatrix.sync.aligned.m8n8.x4.trans.shared.b16 {%0,%1,%2,%3}, [%4];"
                 : "=r"(r[0]), "=r"(r[1]), "=r"(r[2]), "=r"(r[3]) : "r"(addr));
}

__device__ __forceinline__ void mma_bf16(float* c, const uint32_t* a, const uint32_t* b) {
    asm volatile(
        "mma.sync.aligned.m16n8k16.row.col.f32.bf16.bf16.f32 "
        "{%0,%1,%2,%3}, {%4,%5,%6,%7}, {%8,%9}, {%0,%1,%2,%3};"
        : "+f"(c[0]), "+f"(c[1]), "+f"(c[2]), "+f"(c[3])
        : "r"(a[0]), "r"(a[1]), "r"(a[2]), "r"(a[3]), "r"(b[0]), "r"(b[1]));
}

__device__ __forceinline__ void mma_f16(float* c, const uint32_t* a, const uint32_t* b) {
    asm volatile(
        "mma.sync.aligned.m16n8k16.row.col.f32.f16.f16.f32 "
        "{%0,%1,%2,%3}, {%4,%5,%6,%7}, {%8,%9}, {%0,%1,%2,%3};"
        : "+f"(c[0]), "+f"(c[1]), "+f"(c[2]), "+f"(c[3])
        : "r"(a[0]), "r"(a[1]), "r"(a[2]), "r"(a[3]), "r"(b[0]), "r"(b[1]));
}

__device__ __forceinline__ void cp_async16(uint32_t dst, const void* src) {
    asm volatile("cp.async.cg.shared.global [%0], [%1], 16;"
                 :: "r"(dst), "l"(src));
}
__device__ __forceinline__ void cp_commit() {
    asm volatile("cp.async.commit_group;" ::: "memory");
}
template <int N>
__device__ __forceinline__ void cp_wait() {
    asm volatile("cp.async.wait_group %0;" :: "n"(N) : "memory");
}

__device__ __forceinline__ uint32_t pack_half2(__half a, __half b) {
    __half2 h = __halves2half2(a, b);
    return *reinterpret_cast<uint32_t*>(&h);
}

// ---------------------------------------------------------------------------
// x split: fp16 hi/lo (near-exact representation of fp32 x)
// ---------------------------------------------------------------------------
__global__ __launch_bounds__(256) void split_x_kernel(const float* __restrict__ src) {
    int i4 = (blockIdx.x * blockDim.x + threadIdx.x) * 4;
    if (i4 >= NTOK * D_) return;
    float4 v = *(const float4*)(src + i4);
    __half h0 = __float2half_rn(v.x), h1 = __float2half_rn(v.y);
    __half h2 = __float2half_rn(v.z), h3 = __float2half_rn(v.w);
    reinterpret_cast<__half2*>(g_axh + i4)[0] = __halves2half2(h0, h1);
    reinterpret_cast<__half2*>(g_axh + i4)[1] = __halves2half2(h2, h3);
    reinterpret_cast<__half2*>(g_axl + i4)[0] = __halves2half2(
        __float2half_rn(v.x - __half2float(h0)),
        __float2half_rn(v.y - __half2float(h1)));
    reinterpret_cast<__half2*>(g_axl + i4)[1] = __halves2half2(
        __float2half_rn(v.z - __half2float(h2)),
        __float2half_rn(v.w - __half2float(h3)));
}

// all 4 weights -> fp16 single
__global__ __launch_bounds__(256) void split_w_kernel(
    const float* __restrict__ w0, const float* __restrict__ w1,
    const float* __restrict__ w2, const float* __restrict__ w3)
{
    int i4 = (blockIdx.x * blockDim.x + threadIdx.x) * 4;
    if (i4 >= 4 * D_ * D_) return;
    int wi = i4 >> 20;
    int off = i4 & (D_ * D_ - 1);
    const float* src = (wi == 0) ? w0 : (wi == 1) ? w1 : (wi == 2) ? w2 : w3;
    float4 v = *(const float4*)(src + off);
    reinterpret_cast<__half2*>(g_w16[wi] + off)[0] =
        __halves2half2(__float2half_rn(v.x), __float2half_rn(v.y));
    reinterpret_cast<__half2*>(g_w16[wi] + off)[1] =
        __halves2half2(__float2half_rn(v.z), __float2half_rn(v.w));
}

// ---------------------------------------------------------------------------
// RoPE tables
// ---------------------------------------------------------------------------
__global__ void rope_freq_kernel() {
    int j = threadIdx.x;
    if (j < 16) g_freqf[j] = (float)pow(1.0 / 1024.0, (double)j / 15.0);
}

__global__ __launch_bounds__(256) void rope_tables_kernel() {
    int i = blockIdx.x * blockDim.x + threadIdx.x;
    if (i >= T_ * 32) return;
    int t = i >> 5;
    int j = i & 31;
    if (j >= 16) { g_cos[i] = 1.0f; g_sin[i] = 0.0f; return; }
    float theta = (float)t * g_freqf[j];
    const float inv2pi = 0.15915494309189535f;
    const float c1 = 6.28125f;
    const float c2 = 1.9345283508300781e-3f;
    const float c3 = 7.7882876e-7f;
    float n = rintf(theta * inv2pi);
    float r = fmaf(-n, c1, theta);
    r = fmaf(-n, c2, r);
    r = fmaf(-n, c3, r);
    g_cos[i] = cosf(r);
    g_sin[i] = sinf(r);
}

// ---------------------------------------------------------------------------
// Shared GEMM geometry: CTA 256x128, 8 warps (4x2) of 64x64, BK=64,
// 2-stage ring, 144B rows. fp16 2-pass (AhBh + AlBh).
// ---------------------------------------------------------------------------
#define GF_ROWB   144u
#define GF_A_ARR  (256 * 144)
#define GF_B_ARR  (128 * 144)
#define GF_STAGE  (2 * GF_A_ARR + GF_B_ARR)   // 92160
#define GF_SMEM   (2 * GF_STAGE)              // 184320
#define GF_CHUNKS 16

__device__ __forceinline__ void gf_load_stage(
    uint32_t sbase, const __half* a_hi, const __half* a_lo,
    const __half* bh, int k0, int tid)
{
    int seg = tid & 7;
    int r0  = tid >> 3;
    const __half* ah = a_hi + k0 + seg * 8;
    const __half* al = a_lo + k0 + seg * 8;
    const __half* bb = bh + k0 + seg * 8;
    uint32_t d0 = sbase + seg * 16;
#pragma unroll
    for (int rr = 0; rr < 8; rr++) {
        int row = r0 + rr * 32;
        cp_async16(d0 + row * GF_ROWB, ah + (size_t)row * D_);
        cp_async16(d0 + GF_A_ARR + row * GF_ROWB, al + (size_t)row * D_);
    }
#pragma unroll
    for (int rr = 0; rr < 4; rr++) {
        int row = r0 + rr * 32;
        cp_async16(d0 + 2 * GF_A_ARR + row * GF_ROWB, bb + (size_t)row * D_);
    }
}

// fp16 2-pass mainloop body shared by both GEMM kernels
#define GF_MAINLOOP(A_HI, A_LO, B_HI)                                          \
    gf_load_stage(sb, A_HI, A_LO, B_HI, 0, tid);                               \
    cp_commit();                                                               \
    for (int i = 0; i < GF_CHUNKS; i++) {                                      \
        if (i + 1 < GF_CHUNKS) {                                               \
            gf_load_stage(sb + ((i + 1) & 1) * GF_STAGE, A_HI, A_LO, B_HI,     \
                          (i + 1) * 64, tid);                                  \
            cp_commit();                                                       \
            cp_wait<1>();                                                      \
        } else {                                                               \
            cp_wait<0>();                                                      \
        }                                                                      \
        __syncthreads();                                                       \
        uint32_t st = sb + (i & 1) * GF_STAGE;                                 \
        _Pragma("unroll")                                                      \
        for (int ks = 0; ks < 4; ks++) {                                       \
            uint32_t koff = ks * 32;                                           \
            uint32_t fah[4][4], fal[4][4], fbh[4][4];                          \
            _Pragma("unroll")                                                  \
            for (int mt = 0; mt < 4; mt++) {                                   \
                ldsm_x4(fah[mt], st + aoff + koff + mt * 16 * GF_ROWB);        \
                ldsm_x4(fal[mt], st + GF_A_ARR + aoff + koff + mt * 16 * GF_ROWB); \
            }                                                                  \
            _Pragma("unroll")                                                  \
            for (int np = 0; np < 4; np++)                                     \
                ldsm_x4(fbh[np], st + 2 * GF_A_ARR + boff + koff + np * 16 * GF_ROWB); \
            _Pragma("unroll")                                                  \
            for (int np = 0; np < 4; np++)                                     \
                _Pragma("unroll")                                              \
                for (int mt = 0; mt < 4; mt++) {                               \
                    mma_f16(c[mt][np * 2 + 0], fah[mt], fbh[np] + 0);          \
                    mma_f16(c[mt][np * 2 + 1], fah[mt], fbh[np] + 2);          \
                }                                                              \
            _Pragma("unroll")                                                  \
            for (int np = 0; np < 4; np++)                                     \
                _Pragma("unroll")                                              \
                for (int mt = 0; mt < 4; mt++) {                               \
                    mma_f16(c[mt][np * 2 + 0], fal[mt], fbh[np] + 0);          \
                    mma_f16(c[mt][np * 2 + 1], fal[mt], fbh[np] + 2);          \
                }                                                              \
        }                                                                      \
        __syncthreads();                                                       \
    }

// ---------------------------------------------------------------------------
// Q/K GEMM (fp16 2-pass) with fused RMSNorm+RoPE; writes bf16 hi/lo head-major.
// z = 0: Q (scaled), 1: K.
// ---------------------------------------------------------------------------
__global__ __launch_bounds__(256, 1) void gemm_qk_kernel(
    const __half* __restrict__ Ahi, const __half* __restrict__ Alo)
{
    extern __shared__ __align__(128) char smem[];
    uint32_t sb = smem_to_u32(smem);

    const int tid  = threadIdx.x;
    const int wid  = tid >> 5;
    const int lane = tid & 31;
    const int wm = wid & 3;
    const int wn = wid >> 2;
    const int bm = blockIdx.y * 256;
    const int bn = blockIdx.x * 128;
    const int z  = blockIdx.z;   // 0=Q, 1=K

    const __half* a_hi = Ahi + (size_t)bm * D_;
    const __half* a_lo = Alo + (size_t)bm * D_;
    const __half* b_hi = g_w16[z] + (size_t)bn * D_;

    float c[4][8][4];
#pragma unroll
    for (int mt = 0; mt < 4; mt++)
#pragma unroll
        for (int nt = 0; nt < 8; nt++)
#pragma unroll
            for (int r = 0; r < 4; r++) c[mt][nt][r] = 0.0f;

    const int rowA = lane & 15;
    const int kbA  = lane >> 4;
    const int rowB = (lane & 7) + ((lane >> 4) << 3);
    const int kbB  = (lane >> 3) & 1;
    const uint32_t aoff = (uint32_t)(wm * 64 + rowA) * GF_ROWB + kbA * 16;
    const uint32_t boff = (uint32_t)(wn * 64 + rowB) * GF_ROWB + kbB * 16;

    GF_MAINLOOP(a_hi, a_lo, b_hi)

    // fused RMSNorm + RoPE + bf16 split, head-major
    const int erow = bm + wm * 64 + (lane >> 2);
    __nv_bfloat16* dhi = (z == 0) ? g_qhi : g_khi;
    __nv_bfloat16* dlo = (z == 0) ? g_qlo : g_klo;
    const float scale = (z == 0) ? QSCALE : 1.0f;
    const int h = (bn >> 6) + wn;
    const int jbase = (lane & 3) * 2;
#pragma unroll
    for (int mt = 0; mt < 4; mt++) {
#pragma unroll
        for (int rh = 0; rh < 2; rh++) {
            int token = erow + mt * 16 + rh * 8;
            int b = token >> 11, t = token & (T_ - 1);
            float ss = 0.0f;
#pragma unroll
            for (int nt = 0; nt < 8; nt++) {
                float v0 = c[mt][nt][rh * 2], v1 = c[mt][nt][rh * 2 + 1];
                ss = fmaf(v0, v0, ss);
                ss = fmaf(v1, v1, ss);
            }
            ss += __shfl_xor_sync(0xffffffffu, ss, 1);
            ss += __shfl_xor_sync(0xffffffffu, ss, 2);
            float rn = rsqrtf(ss * (1.0f / 64.0f) + 1e-6f) * scale;
            size_t ob = (((size_t)(b * H_ + h)) * T_ + t) * HD_;
            const float* ct = g_cos + t * 32;
            const float* stb = g_sin + t * 32;
#pragma unroll
            for (int nt = 0; nt < 4; nt++) {
                int j0 = jbase + (nt >> 1) * 16 + (nt & 1) * 8;
                float x1a = c[mt][nt][rh * 2]     * rn;
                float x1b = c[mt][nt][rh * 2 + 1] * rn;
                float x2a = c[mt][nt + 4][rh * 2]     * rn;
                float x2b = c[mt][nt + 4][rh * 2 + 1] * rn;
                float ca = ct[j0],     sa = stb[j0];
                float cb = ct[j0 + 1], sb2 = stb[j0 + 1];
                float y1a = x1a * ca + x2a * sa;
                float y2a = -x1a * sa + x2a * ca;
                float y1b = x1b * cb + x2b * sb2;
                float y2b = -x1b * sb2 + x2b * cb;
                __nv_bfloat16 h1a = __float2bfloat16(y1a), h1b = __float2bfloat16(y1b);
                __nv_bfloat16 h2a = __float2bfloat16(y2a), h2b = __float2bfloat16(y2b);
                *reinterpret_cast<__nv_bfloat162*>(dhi + ob + j0)      = __nv_bfloat162(h1a, h1b);
                *reinterpret_cast<__nv_bfloat162*>(dhi + ob + j0 + 32) = __nv_bfloat162(h2a, h2b);
                *reinterpret_cast<__nv_bfloat162*>(dlo + ob + j0) = __nv_bfloat162(
                    __float2bfloat16(y1a - __bfloat162float(h1a)),
                    __float2bfloat16(y1b - __bfloat162float(h1b)));
                *reinterpret_cast<__nv_bfloat162*>(dlo + ob + j0 + 32) = __nv_bfloat162(
                    __float2bfloat16(y2a - __bfloat162float(h2a)),
                    __float2bfloat16(y2b - __bfloat162float(h2b)));
            }
        }
    }
}

// ---------------------------------------------------------------------------
// fp16 2-pass GEMM for V projection (mode 0) and wo (mode 1).
// ---------------------------------------------------------------------------
__global__ __launch_bounds__(256, 1) void gemm_f16_kernel(
    const __half* __restrict__ Ahi, const __half* __restrict__ Alo,
    const __half* __restrict__ Bh, int mode, float* Cout)
{
    extern __shared__ __align__(128) char smem[];
    uint32_t sb = smem_to_u32(smem);

    const int tid  = threadIdx.x;
    const int wid  = tid >> 5;
    const int lane = tid & 31;
    const int wm = wid & 3;
    const int wn = wid >> 2;
    const int bm = blockIdx.y * 256;
    const int bn = blockIdx.x * 128;

    const __half* a_hi = Ahi + (size_t)bm * D_;
    const __half* a_lo = Alo + (size_t)bm * D_;
    const __half* b_hi = Bh + (size_t)bn * D_;

    float c[4][8][4];
#pragma unroll
    for (int mt = 0; mt < 4; mt++)
#pragma unroll
        for (int nt = 0; nt < 8; nt++)
#pragma unroll
            for (int r = 0; r < 4; r++) c[mt][nt][r] = 0.0f;

    const int rowA = lane & 15;
    const int kbA  = lane >> 4;
    const int rowB = (lane & 7) + ((lane >> 4) << 3);
    const int kbB  = (lane >> 3) & 1;
    const uint32_t aoff = (uint32_t)(wm * 64 + rowA) * GF_ROWB + kbA * 16;
    const uint32_t boff = (uint32_t)(wn * 64 + rowB) * GF_ROWB + kbB * 16;

    GF_MAINLOOP(a_hi, a_lo, b_hi)

    const int erow = bm + wm * 64 + (lane >> 2);
    const int ecol = bn + wn * 64 + (lane & 3) * 2;

    if (mode == 0) {
        // V: head-major fp16 single
#pragma unroll
        for (int mt = 0; mt < 4; mt++)
#pragma unroll
            for (int nt = 0; nt < 8; nt++) {
                int cc = ecol + (nt >> 1) * 16 + (nt & 1) * 8;
                int h = cc >> 6, hd = cc & 63;
#pragma unroll
                for (int rh = 0; rh < 2; rh++) {
                    int token = erow + mt * 16 + rh * 8;
                    int b = token >> 11, t = token & (T_ - 1);
                    size_t oi = (((size_t)(b * H_ + h)) * T_ + t) * HD_ + hd;
                    *reinterpret_cast<__half2*>(g_v16 + oi) = __halves2half2(
                        __float2half_rn(c[mt][nt][rh * 2]),
                        __float2half_rn(c[mt][nt][rh * 2 + 1]));
                }
            }
    } else {
        // wo: fp32 out
#pragma unroll
        for (int mt = 0; mt < 4; mt++)
#pragma unroll
            for (int nt = 0; nt < 8; nt++) {
                int r0 = erow + mt * 16;
                int cc = ecol + (nt >> 1) * 16 + (nt & 1) * 8;
                *(float2*)&Cout[(size_t)r0 * D_ + cc]       = make_float2(c[mt][nt][0], c[mt][nt][1]);
                *(float2*)&Cout[(size_t)(r0 + 8) * D_ + cc] = make_float2(c[mt][nt][2], c[mt][nt][3]);
            }
    }
}

// ---------------------------------------------------------------------------
// Flash attention: S = bf16x3 (Q/K hi/lo), PV = fp16 2-pass (P hi/lo x V).
// KV stage: Khi, Klo (bf16), V (fp16). exp2 softmax.
// Epilogue writes fp16 hi/lo attn-out (token-major) for the wo GEMM.
// ---------------------------------------------------------------------------
#define FROWB   144u
#define FQ_SIZE (128 * 144)
#define FKV_OFF (2 * FQ_SIZE)
#define FKV_ARR (128 * 144)
#define FSTAGE  (3 * FKV_ARR)              // 55296
#define FMMA_SMEM (FKV_OFF + 2 * FSTAGE)   // 147456

__device__ __forceinline__ void f_load_kv(
    uint32_t dst, const __nv_bfloat16* kh, const __nv_bfloat16* kl,
    const __half* vh, size_t goff, int tid)
{
    int seg = tid & 7, r0 = tid >> 3;
    const __nv_bfloat16* s0 = kh + goff + seg * 8;
    const __nv_bfloat16* s1 = kl + goff + seg * 8;
    const __half* s2 = vh + goff + seg * 8;
    uint32_t d = dst + seg * 16;
#pragma unroll
    for (int rr = 0; rr < 4; rr++) {
        int row = r0 + rr * 32;
        cp_async16(d + row * FROWB, s0 + row * HD_);
        cp_async16(d + FKV_ARR + row * FROWB, s1 + row * HD_);
        cp_async16(d + 2 * FKV_ARR + row * FROWB, s2 + row * HD_);
    }
}

__global__ __launch_bounds__(256, 1) void flash_mma_kernel(
    __half* __restrict__ Ohi, __half* __restrict__ Olo)
{
    extern __shared__ __align__(128) char fsm[];
    uint32_t sb = smem_to_u32(fsm);
    const int tid = threadIdx.x, wid = tid >> 5, lane = tid & 31;
    const int bh = blockIdx.x;
    const int qt = 15 - blockIdx.y;
    const int b = bh >> 4, h = bh & 15;
    const size_t headoff = (size_t)bh * T_ * HD_;
    const int nkt = qt + 1;

    {
        int seg = tid & 7, r0 = tid >> 3;
        const __nv_bfloat16* q0 = g_qhi + headoff + (size_t)qt * 128 * HD_ + seg * 8;
        const __nv_bfloat16* q1 = g_qlo + headoff + (size_t)qt * 128 * HD_ + seg * 8;
#pragma unroll
        for (int rr = 0; rr < 4; rr++) {
            int row = r0 + rr * 32;
            cp_async16(sb + row * FROWB + seg * 16, q0 + row * HD_);
            cp_async16(sb + FQ_SIZE + row * FROWB + seg * 16, q1 + row * HD_);
        }
    }
    f_load_kv(sb + FKV_OFF, g_khi, g_klo, g_v16, headoff, tid);
    cp_commit();

    uint32_t fqh[4][4], fql[4][4];
    float o[8][4];
#pragma unroll
    for (int nt = 0; nt < 8; nt++)
#pragma unroll
        for (int r = 0; r < 4; r++) o[nt][r] = 0.0f;
    float m0 = -1e30f, m1 = -1e30f, l0 = 0.0f, l1 = 0.0f;

    const uint32_t qrow_off = (uint32_t)(wid * 16 + (lane & 15)) * FROWB + (lane >> 4) * 16;
    const uint32_t krow_off = (uint32_t)((lane & 7) + ((lane >> 4) << 3)) * FROWB
                              + ((lane >> 3) & 1) * 16;
    const uint32_t vrow_off = (uint32_t)(lane & 15) * FROWB + (lane >> 4) * 16;

    for (int jt = 0; jt < nkt; jt++) {
        if (jt + 1 < nkt) {
            f_load_kv(sb + FKV_OFF + ((jt + 1) & 1) * FSTAGE, g_khi, g_klo, g_v16,
                      headoff + (size_t)(jt + 1) * 128 * HD_, tid);
            cp_commit();
            cp_wait<1>();
        } else {
            cp_wait<0>();
        }
        __syncthreads();

        if (jt == 0) {
#pragma unroll
            for (int ks = 0; ks < 4; ks++) {
                ldsm_x4(fqh[ks], sb + qrow_off + ks * 32);
                ldsm_x4(fql[ks], sb + FQ_SIZE + qrow_off + ks * 32);
            }
        }

        uint32_t st = sb + FKV_OFF + (jt & 1) * FSTAGE;

        float s[16][4];
#pragma unroll
        for (int nt = 0; nt < 16; nt++)
#pragma unroll
            for (int r = 0; r < 4; r++) s[nt][r] = 0.0f;

#pragma unroll
        for (int np = 0; np < 8; np++) {
#pragma unroll
            for (int ks = 0; ks < 4; ks++) {
                uint32_t addr = st + krow_off + np * 16 * FROWB + ks * 32;
                uint32_t fk[4];
                ldsm_x4(fk, addr);
                mma_bf16(s[2 * np],     fqh[ks], fk + 0);
                mma_bf16(s[2 * np + 1], fqh[ks], fk + 2);
                mma_bf16(s[2 * np],     fql[ks], fk + 0);
                mma_bf16(s[2 * np + 1], fql[ks], fk + 2);
                ldsm_x4(fk, addr + FKV_ARR);
                mma_bf16(s[2 * np],     fqh[ks], fk + 0);
                mma_bf16(s[2 * np + 1], fqh[ks], fk + 2);
            }
        }

        if (jt == qt) {
            int grow = qt * 128 + wid * 16 + (lane >> 2);
            int gc0 = jt * 128 + (lane & 3) * 2;
#pragma unroll
            for (int nt = 0; nt < 16; nt++) {
                int cc = gc0 + nt * 8;
                if (cc > grow)          s[nt][0] = -1e30f;
                if (cc + 1 > grow)      s[nt][1] = -1e30f;
                if (cc > grow + 8)      s[nt][2] = -1e30f;
                if (cc + 1 > grow + 8)  s[nt][3] = -1e30f;
            }
        }

        float mx0 = -1e30f, mx1 = -1e30f;
#pragma unroll
        for (int nt = 0; nt < 16; nt++) {
            mx0 = fmaxf(mx0, fmaxf(s[nt][0], s[nt][1]));
            mx1 = fmaxf(mx1, fmaxf(s[nt][2], s[nt][3]));
        }
        mx0 = fmaxf(mx0, __shfl_xor_sync(0xffffffffu, mx0, 1));
        mx0 = fmaxf(mx0, __shfl_xor_sync(0xffffffffu, mx0, 2));
        mx1 = fmaxf(mx1, __shfl_xor_sync(0xffffffffu, mx1, 1));
        mx1 = fmaxf(mx1, __shfl_xor_sync(0xffffffffu, mx1, 2));
        float mn0 = fmaxf(m0, mx0), mn1 = fmaxf(m1, mx1);
        float al0 = exp2f(m0 - mn0), al1 = exp2f(m1 - mn1);
        float rs0 = 0.0f, rs1 = 0.0f;
#pragma unroll
        for (int nt = 0; nt < 16; nt++) {
            s[nt][0] = exp2f(s[nt][0] - mn0);
            s[nt][1] = exp2f(s[nt][1] - mn0);
            s[nt][2] = exp2f(s[nt][2] - mn1);
            s[nt][3] = exp2f(s[nt][3] - mn1);
            rs0 += s[nt][0] + s[nt][1];
            rs1 += s[nt][2] + s[nt][3];
        }
        rs0 += __shfl_xor_sync(0xffffffffu, rs0, 1);
        rs0 += __shfl_xor_sync(0xffffffffu, rs0, 2);
        rs1 += __shfl_xor_sync(0xffffffffu, rs1, 1);
        rs1 += __shfl_xor_sync(0xffffffffu, rs1, 2);
        l0 = l0 * al0 + rs0; m0 = mn0;
        l1 = l1 * al1 + rs1; m1 = mn1;
#pragma unroll
        for (int nt = 0; nt < 8; nt++) {
            o[nt][0] *= al0; o[nt][1] *= al0;
            o[nt][2] *= al1; o[nt][3] *= al1;
        }

        // P -> fp16 hi/lo A-fragments
        uint32_t fph[8][4], fpl[8][4];
#pragma unroll
        for (int f = 0; f < 8; f++) {
#pragma unroll
            for (int half = 0; half < 2; half++) {
                int nt = 2 * f + half;
#pragma unroll
                for (int rh = 0; rh < 2; rh++) {
                    float p0 = s[nt][rh * 2], p1 = s[nt][rh * 2 + 1];
                    __half h0 = __float2half_rn(p0), h1 = __float2half_rn(p1);
                    fph[f][half * 2 + rh] = pack_half2(h0, h1);
                    fpl[f][half * 2 + rh] = pack_half2(
                        __float2half_rn(p0 - __half2float(h0)),
                        __float2half_rn(p1 - __half2float(h1)));
                }
            }
        }

        // O += P V (fp16 2-pass)
#pragma unroll
        for (int nh = 0; nh < 4; nh++) {
#pragma unroll
            for (int ks = 0; ks < 8; ks++) {
                uint32_t addr = st + 2 * FKV_ARR + vrow_off + ks * 16 * FROWB + nh * 32;
                uint32_t fv[4];
                ldsm_x4_t(fv, addr);
                mma_f16(o[2 * nh],     fph[ks], fv + 0);
                mma_f16(o[2 * nh + 1], fph[ks], fv + 2);
                mma_f16(o[2 * nh],     fpl[ks], fv + 0);
                mma_f16(o[2 * nh + 1], fpl[ks], fv + 2);
            }
        }
        __syncthreads();
    }

    // epilogue: normalize + fp16 hi/lo split, token-major [b][t][h*64+hd]
    float inv0 = 1.0f / l0, inv1 = 1.0f / l1;
    int row = qt * 128 + wid * 16 + (lane >> 2);
    size_t base0 = ((size_t)b * T_ + row) * D_ + h * 64 + (lane & 3) * 2;
    size_t base1 = base0 + (size_t)8 * D_;
#pragma unroll
    for (int nt = 0; nt < 8; nt++) {
        float v0 = o[nt][0] * inv0, v1 = o[nt][1] * inv0;
        float v2 = o[nt][2] * inv1, v3 = o[nt][3] * inv1;
        __half h0 = __float2half_rn(v0), h1 = __float2half_rn(v1);
        __half h2 = __float2half_rn(v2), h3 = __float2half_rn(v3);
        *reinterpret_cast<__half2*>(Ohi + base0 + nt * 8) = __halves2half2(h0, h1);
        *reinterpret_cast<__half2*>(Ohi + base1 + nt * 8) = __halves2half2(h2, h3);
        *reinterpret_cast<__half2*>(Olo + base0 + nt * 8) = __halves2half2(
            __float2half_rn(v0 - __half2float(h0)),
            __float2half_rn(v1 - __half2float(h1)));
        *reinterpret_cast<__half2*>(Olo + base1 + nt * 8) = __halves2half2(
            __float2half_rn(v2 - __half2float(h2)),
            __float2half_rn(v3 - __half2float(h3)));
    }
}

// ---------------------------------------------------------------------------
// Launch
// ---------------------------------------------------------------------------
extern "C" void kernel_launch(void* const* d_in, const int* in_sizes, int n_in,
                              void* d_out, int out_size)
{
    (void)in_sizes; (void)n_in; (void)out_size;
    const float* x  = (const float*)d_in[0];
    const float* w[4] = {(const float*)d_in[1], (const float*)d_in[2],
                         (const float*)d_in[3], (const float*)d_in[4]};
    float* out = (float*)d_out;

    __half *axh, *axl, *w16;
    cudaGetSymbolAddress((void**)&axh, g_axh);
    cudaGetSymbolAddress((void**)&axl, g_axl);
    cudaGetSymbolAddress((void**)&w16, g_w16);

    cudaFuncSetAttribute(gemm_qk_kernel,
                         cudaFuncAttributeMaxDynamicSharedMemorySize, GF_SMEM);
    cudaFuncSetAttribute(gemm_f16_kernel,
                         cudaFuncAttributeMaxDynamicSharedMemorySize, GF_SMEM);
    cudaFuncSetAttribute(flash_mma_kernel,
                         cudaFuncAttributeMaxDynamicSharedMemorySize, FMMA_SMEM);

    rope_freq_kernel<<<1, 16>>>();
    rope_tables_kernel<<<(T_ * 32 + 255) / 256, 256>>>();

    split_x_kernel<<<(NTOK * D_ / 4 + 255) / 256, 256>>>(x);
    split_w_kernel<<<(4 * D_ * D_ / 4 + 255) / 256, 256>>>(w[0], w[1], w[2], w[3]);

    // Q/K projections (fp16 2-pass, fused norm+rope epilogue -> bf16 hi/lo)
    gemm_qk_kernel<<<dim3(D_ / 128, NTOK / 256, 2), 256, GF_SMEM>>>(axh, axl);

    // V projection (fp16 2-pass) -> head-major fp16
    gemm_f16_kernel<<<dim3(D_ / 128, NTOK / 256, 1), 256, GF_SMEM>>>(
        axh, axl, w16 + 2 * (size_t)D_ * D_, 0, out);

    // flash: writes fp16 hi/lo attn-out into axh/axl
    flash_mma_kernel<<<dim3(BH_, T_ / 128), 256, FMMA_SMEM>>>(axh, axl);

    // wo projection (fp16 2-pass) -> fp32 out
    gemm_f16_kernel<<<dim3(D_ / 128, NTOK / 256, 1), 256, GF_SMEM>>>(
        axh, axl, w16 + 3 * (size_t)D_ * D_, 1, out);
}

// round 17
// speedup vs baseline: 1.5097x; 1.0616x over previous
#include <cuda_runtime.h>
#include <cuda_bf16.h>
#include <cuda_fp16.h>
#include <math.h>
#include <stdint.h>

// Problem constants
#define B_   4
#define T_   2048
#define D_   1024
#define H_   16
#define HD_  64
#define NTOK (B_ * T_)   // 8192
#define BH_  (B_ * H_)   // 64

// ---------------------------------------------------------------------------
// Scratch (device globals: allocation-free rule)
// ---------------------------------------------------------------------------
__device__ float g_cos[T_ * 32];
__device__ float g_sin[T_ * 32];
__device__ float g_freqf[16];

// fp16 x split (projections); later reused as fp16 attn-out split (wo GEMM)
__device__ __half g_axh[NTOK * D_];
__device__ __half g_axl[NTOK * D_];
// all 4 weights fp16 single
__device__ __half g_w16[4][D_ * D_];

// head-major fp16 for flash: Q hi/lo, K hi/lo (lo unused by flash), V single
__device__ __half g_q16h[BH_ * T_ * HD_];
__device__ __half g_q16l[BH_ * T_ * HD_];
__device__ __half g_k16h[BH_ * T_ * HD_];
__device__ __half g_k16l[BH_ * T_ * HD_];
__device__ __half g_v16[BH_ * T_ * HD_];

#define QSCALE (0.125f * 1.4426950408889634f)

// ---------------------------------------------------------------------------
// PTX helpers (base compute_103 target: mma.sync / ldmatrix / cp.async only)
// ---------------------------------------------------------------------------
__device__ __forceinline__ uint32_t smem_to_u32(const void* p) {
    uint32_t a;
    asm("{ .reg .u64 t; cvta.to.shared.u64 t, %1; cvt.u32.u64 %0, t; }"
        : "=r"(a) : "l"(p));
    return a;
}

__device__ __forceinline__ void ldsm_x4(uint32_t* r, uint32_t addr) {
    asm volatile("ldmatrix.sync.aligned.m8n8.x4.shared.b16 {%0,%1,%2,%3}, [%4];"
                 : "=r"(r[0]), "=r"(r[1]), "=r"(r[2]), "=r"(r[3]) : "r"(addr));
}

__device__ __forceinline__ void ldsm_x4_t(uint32_t* r, uint32_t addr) {
    asm volatile("ldmatrix.sync.aligned.m8n8.x4.trans.shared.b16 {%0,%1,%2,%3}, [%4];"
                 : "=r"(r[0]), "=r"(r[1]), "=r"(r[2]), "=r"(r[3]) : "r"(addr));
}

__device__ __forceinline__ void mma_f16(float* c, const uint32_t* a, const uint32_t* b) {
    asm volatile(
        "mma.sync.aligned.m16n8k16.row.col.f32.f16.f16.f32 "
        "{%0,%1,%2,%3}, {%4,%5,%6,%7}, {%8,%9}, {%0,%1,%2,%3};"
        : "+f"(c[0]), "+f"(c[1]), "+f"(c[2]), "+f"(c[3])
        : "r"(a[0]), "r"(a[1]), "r"(a[2]), "r"(a[3]), "r"(b[0]), "r"(b[1]));
}

__device__ __forceinline__ void cp_async16(uint32_t dst, const void* src) {
    asm volatile("cp.async.cg.shared.global [%0], [%1], 16;"
                 :: "r"(dst), "l"(src));
}
__device__ __forceinline__ void cp_commit() {
    asm volatile("cp.async.commit_group;" ::: "memory");
}
template <int N>
__device__ __forceinline__ void cp_wait() {
    asm volatile("cp.async.wait_group %0;" :: "n"(N) : "memory");
}

__device__ __forceinline__ uint32_t pack_half2(__half a, __half b) {
    __half2 h = __halves2half2(a, b);
    return *reinterpret_cast<uint32_t*>(&h);
}

// ---------------------------------------------------------------------------
// x split: fp16 hi/lo (near-exact representation of fp32 x)
// ---------------------------------------------------------------------------
__global__ __launch_bounds__(256) void split_x_kernel(const float* __restrict__ src) {
    int i4 = (blockIdx.x * blockDim.x + threadIdx.x) * 4;
    if (i4 >= NTOK * D_) return;
    float4 v = *(const float4*)(src + i4);
    __half h0 = __float2half_rn(v.x), h1 = __float2half_rn(v.y);
    __half h2 = __float2half_rn(v.z), h3 = __float2half_rn(v.w);
    reinterpret_cast<__half2*>(g_axh + i4)[0] = __halves2half2(h0, h1);
    reinterpret_cast<__half2*>(g_axh + i4)[1] = __halves2half2(h2, h3);
    reinterpret_cast<__half2*>(g_axl + i4)[0] = __halves2half2(
        __float2half_rn(v.x - __half2float(h0)),
        __float2half_rn(v.y - __half2float(h1)));
    reinterpret_cast<__half2*>(g_axl + i4)[1] = __halves2half2(
        __float2half_rn(v.z - __half2float(h2)),
        __float2half_rn(v.w - __half2float(h3)));
}

// all 4 weights -> fp16 single
__global__ __launch_bounds__(256) void split_w_kernel(
    const float* __restrict__ w0, const float* __restrict__ w1,
    const float* __restrict__ w2, const float* __restrict__ w3)
{
    int i4 = (blockIdx.x * blockDim.x + threadIdx.x) * 4;
    if (i4 >= 4 * D_ * D_) return;
    int wi = i4 >> 20;
    int off = i4 & (D_ * D_ - 1);
    const float* src = (wi == 0) ? w0 : (wi == 1) ? w1 : (wi == 2) ? w2 : w3;
    float4 v = *(const float4*)(src + off);
    reinterpret_cast<__half2*>(g_w16[wi] + off)[0] =
        __halves2half2(__float2half_rn(v.x), __float2half_rn(v.y));
    reinterpret_cast<__half2*>(g_w16[wi] + off)[1] =
        __halves2half2(__float2half_rn(v.z), __float2half_rn(v.w));
}

// ---------------------------------------------------------------------------
// RoPE tables
// ---------------------------------------------------------------------------
__global__ void rope_freq_kernel() {
    int j = threadIdx.x;
    if (j < 16) g_freqf[j] = (float)pow(1.0 / 1024.0, (double)j / 15.0);
}

__global__ __launch_bounds__(256) void rope_tables_kernel() {
    int i = blockIdx.x * blockDim.x + threadIdx.x;
    if (i >= T_ * 32) return;
    int t = i >> 5;
    int j = i & 31;
    if (j >= 16) { g_cos[i] = 1.0f; g_sin[i] = 0.0f; return; }
    float theta = (float)t * g_freqf[j];
    const float inv2pi = 0.15915494309189535f;
    const float c1 = 6.28125f;
    const float c2 = 1.9345283508300781e-3f;
    const float c3 = 7.7882876e-7f;
    float n = rintf(theta * inv2pi);
    float r = fmaf(-n, c1, theta);
    r = fmaf(-n, c2, r);
    r = fmaf(-n, c3, r);
    g_cos[i] = cosf(r);
    g_sin[i] = sinf(r);
}

// ---------------------------------------------------------------------------
// Shared GEMM geometry: CTA 256x128, 8 warps (4x2) of 64x64, BK=64,
// 2-stage ring, 144B rows. fp16 2-pass (AhBh + AlBh).
// ---------------------------------------------------------------------------
#define GF_ROWB   144u
#define GF_A_ARR  (256 * 144)
#define GF_B_ARR  (128 * 144)
#define GF_STAGE  (2 * GF_A_ARR + GF_B_ARR)   // 92160
#define GF_SMEM   (2 * GF_STAGE)              // 184320
#define GF_CHUNKS 16

__device__ __forceinline__ void gf_load_stage(
    uint32_t sbase, const __half* a_hi, const __half* a_lo,
    const __half* bh, int k0, int tid)
{
    int seg = tid & 7;
    int r0  = tid >> 3;
    const __half* ah = a_hi + k0 + seg * 8;
    const __half* al = a_lo + k0 + seg * 8;
    const __half* bb = bh + k0 + seg * 8;
    uint32_t d0 = sbase + seg * 16;
#pragma unroll
    for (int rr = 0; rr < 8; rr++) {
        int row = r0 + rr * 32;
        cp_async16(d0 + row * GF_ROWB, ah + (size_t)row * D_);
        cp_async16(d0 + GF_A_ARR + row * GF_ROWB, al + (size_t)row * D_);
    }
#pragma unroll
    for (int rr = 0; rr < 4; rr++) {
        int row = r0 + rr * 32;
        cp_async16(d0 + 2 * GF_A_ARR + row * GF_ROWB, bb + (size_t)row * D_);
    }
}

// fp16 2-pass mainloop body shared by both GEMM kernels
#define GF_MAINLOOP(A_HI, A_LO, B_HI)                                          \
    gf_load_stage(sb, A_HI, A_LO, B_HI, 0, tid);                               \
    cp_commit();                                                               \
    for (int i = 0; i < GF_CHUNKS; i++) {                                      \
        if (i + 1 < GF_CHUNKS) {                                               \
            gf_load_stage(sb + ((i + 1) & 1) * GF_STAGE, A_HI, A_LO, B_HI,     \
                          (i + 1) * 64, tid);                                  \
            cp_commit();                                                       \
            cp_wait<1>();                                                      \
        } else {                                                               \
            cp_wait<0>();                                                      \
        }                                                                      \
        __syncthreads();                                                       \
        uint32_t st = sb + (i & 1) * GF_STAGE;                                 \
        _Pragma("unroll")                                                      \
        for (int ks = 0; ks < 4; ks++) {                                       \
            uint32_t koff = ks * 32;                                           \
            uint32_t fah[4][4], fal[4][4], fbh[4][4];                          \
            _Pragma("unroll")                                                  \
            for (int mt = 0; mt < 4; mt++) {                                   \
                ldsm_x4(fah[mt], st + aoff + koff + mt * 16 * GF_ROWB);        \
                ldsm_x4(fal[mt], st + GF_A_ARR + aoff + koff + mt * 16 * GF_ROWB); \
            }                                                                  \
            _Pragma("unroll")                                                  \
            for (int np = 0; np < 4; np++)                                     \
                ldsm_x4(fbh[np], st + 2 * GF_A_ARR + boff + koff + np * 16 * GF_ROWB); \
            _Pragma("unroll")                                                  \
            for (int np = 0; np < 4; np++)                                     \
                _Pragma("unroll")                                              \
                for (int mt = 0; mt < 4; mt++) {                               \
                    mma_f16(c[mt][np * 2 + 0], fah[mt], fbh[np] + 0);          \
                    mma_f16(c[mt][np * 2 + 1], fah[mt], fbh[np] + 2);          \
                }                                                              \
            _Pragma("unroll")                                                  \
            for (int np = 0; np < 4; np++)                                     \
                _Pragma("unroll")                                              \
                for (int mt = 0; mt < 4; mt++) {                               \
                    mma_f16(c[mt][np * 2 + 0], fal[mt], fbh[np] + 0);          \
                    mma_f16(c[mt][np * 2 + 1], fal[mt], fbh[np] + 2);          \
                }                                                              \
        }                                                                      \
        __syncthreads();                                                       \
    }

// ---------------------------------------------------------------------------
// Q/K GEMM (fp16 2-pass) with fused RMSNorm+RoPE; writes fp16 hi/lo head-major.
// z = 0: Q (scaled), 1: K. Epilogues symmetric (only pointers/scale differ).
// ---------------------------------------------------------------------------
__global__ __launch_bounds__(256, 1) void gemm_qk_kernel(
    const __half* __restrict__ Ahi, const __half* __restrict__ Alo)
{
    extern __shared__ __align__(128) char smem[];
    uint32_t sb = smem_to_u32(smem);

    const int tid  = threadIdx.x;
    const int wid  = tid >> 5;
    const int lane = tid & 31;
    const int wm = wid & 3;
    const int wn = wid >> 2;
    const int bm = blockIdx.y * 256;
    const int bn = blockIdx.x * 128;
    const int z  = blockIdx.z;   // 0=Q, 1=K

    const __half* a_hi = Ahi + (size_t)bm * D_;
    const __half* a_lo = Alo + (size_t)bm * D_;
    const __half* b_hi = g_w16[z] + (size_t)bn * D_;

    float c[4][8][4];
#pragma unroll
    for (int mt = 0; mt < 4; mt++)
#pragma unroll
        for (int nt = 0; nt < 8; nt++)
#pragma unroll
            for (int r = 0; r < 4; r++) c[mt][nt][r] = 0.0f;

    const int rowA = lane & 15;
    const int kbA  = lane >> 4;
    const int rowB = (lane & 7) + ((lane >> 4) << 3);
    const int kbB  = (lane >> 3) & 1;
    const uint32_t aoff = (uint32_t)(wm * 64 + rowA) * GF_ROWB + kbA * 16;
    const uint32_t boff = (uint32_t)(wn * 64 + rowB) * GF_ROWB + kbB * 16;

    GF_MAINLOOP(a_hi, a_lo, b_hi)

    // fused RMSNorm + RoPE + fp16 hi/lo split, head-major (symmetric Q/K)
    const int erow = bm + wm * 64 + (lane >> 2);
    __half* dhi = (z == 0) ? g_q16h : g_k16h;
    __half* dlo = (z == 0) ? g_q16l : g_k16l;
    const float scale = (z == 0) ? QSCALE : 1.0f;
    const int h = (bn >> 6) + wn;
    const int jbase = (lane & 3) * 2;
#pragma unroll
    for (int mt = 0; mt < 4; mt++) {
#pragma unroll
        for (int rh = 0; rh < 2; rh++) {
            int token = erow + mt * 16 + rh * 8;
            int b = token >> 11, t = token & (T_ - 1);
            float ss = 0.0f;
#pragma unroll
            for (int nt = 0; nt < 8; nt++) {
                float v0 = c[mt][nt][rh * 2], v1 = c[mt][nt][rh * 2 + 1];
                ss = fmaf(v0, v0, ss);
                ss = fmaf(v1, v1, ss);
            }
            ss += __shfl_xor_sync(0xffffffffu, ss, 1);
            ss += __shfl_xor_sync(0xffffffffu, ss, 2);
            float rn = rsqrtf(ss * (1.0f / 64.0f) + 1e-6f) * scale;
            size_t ob = (((size_t)(b * H_ + h)) * T_ + t) * HD_;
            const float* ct = g_cos + t * 32;
            const float* stb = g_sin + t * 32;
#pragma unroll
            for (int nt = 0; nt < 4; nt++) {
                int j0 = jbase + (nt >> 1) * 16 + (nt & 1) * 8;
                float x1a = c[mt][nt][rh * 2]     * rn;
                float x1b = c[mt][nt][rh * 2 + 1] * rn;
                float x2a = c[mt][nt + 4][rh * 2]     * rn;
                float x2b = c[mt][nt + 4][rh * 2 + 1] * rn;
                float ca = ct[j0],     sa = stb[j0];
                float cb = ct[j0 + 1], sb2 = stb[j0 + 1];
                float y1a = x1a * ca + x2a * sa;
                float y2a = -x1a * sa + x2a * ca;
                float y1b = x1b * cb + x2b * sb2;
                float y2b = -x1b * sb2 + x2b * cb;
                __half h1a = __float2half_rn(y1a), h1b = __float2half_rn(y1b);
                __half h2a = __float2half_rn(y2a), h2b = __float2half_rn(y2b);
                *reinterpret_cast<__half2*>(dhi + ob + j0)      = __halves2half2(h1a, h1b);
                *reinterpret_cast<__half2*>(dhi + ob + j0 + 32) = __halves2half2(h2a, h2b);
                *reinterpret_cast<__half2*>(dlo + ob + j0) = __halves2half2(
                    __float2half_rn(y1a - __half2float(h1a)),
                    __float2half_rn(y1b - __half2float(h1b)));
                *reinterpret_cast<__half2*>(dlo + ob + j0 + 32) = __halves2half2(
                    __float2half_rn(y2a - __half2float(h2a)),
                    __float2half_rn(y2b - __half2float(h2b)));
            }
        }
    }
}

// ---------------------------------------------------------------------------
// fp16 2-pass GEMM for V projection (mode 0) and wo (mode 1).
// ---------------------------------------------------------------------------
__global__ __launch_bounds__(256, 1) void gemm_f16_kernel(
    const __half* __restrict__ Ahi, const __half* __restrict__ Alo,
    const __half* __restrict__ Bh, int mode, float* Cout)
{
    extern __shared__ __align__(128) char smem[];
    uint32_t sb = smem_to_u32(smem);

    const int tid  = threadIdx.x;
    const int wid  = tid >> 5;
    const int lane = tid & 31;
    const int wm = wid & 3;
    const int wn = wid >> 2;
    const int bm = blockIdx.y * 256;
    const int bn = blockIdx.x * 128;

    const __half* a_hi = Ahi + (size_t)bm * D_;
    const __half* a_lo = Alo + (size_t)bm * D_;
    const __half* b_hi = Bh + (size_t)bn * D_;

    float c[4][8][4];
#pragma unroll
    for (int mt = 0; mt < 4; mt++)
#pragma unroll
        for (int nt = 0; nt < 8; nt++)
#pragma unroll
            for (int r = 0; r < 4; r++) c[mt][nt][r] = 0.0f;

    const int rowA = lane & 15;
    const int kbA  = lane >> 4;
    const int rowB = (lane & 7) + ((lane >> 4) << 3);
    const int kbB  = (lane >> 3) & 1;
    const uint32_t aoff = (uint32_t)(wm * 64 + rowA) * GF_ROWB + kbA * 16;
    const uint32_t boff = (uint32_t)(wn * 64 + rowB) * GF_ROWB + kbB * 16;

    GF_MAINLOOP(a_hi, a_lo, b_hi)

    const int erow = bm + wm * 64 + (lane >> 2);
    const int ecol = bn + wn * 64 + (lane & 3) * 2;

    if (mode == 0) {
        // V: head-major fp16 single
#pragma unroll
        for (int mt = 0; mt < 4; mt++)
#pragma unroll
            for (int nt = 0; nt < 8; nt++) {
                int cc = ecol + (nt >> 1) * 16 + (nt & 1) * 8;
                int h = cc >> 6, hd = cc & 63;
#pragma unroll
                for (int rh = 0; rh < 2; rh++) {
                    int token = erow + mt * 16 + rh * 8;
                    int b = token >> 11, t = token & (T_ - 1);
                    size_t oi = (((size_t)(b * H_ + h)) * T_ + t) * HD_ + hd;
                    *reinterpret_cast<__half2*>(g_v16 + oi) = __halves2half2(
                        __float2half_rn(c[mt][nt][rh * 2]),
                        __float2half_rn(c[mt][nt][rh * 2 + 1]));
                }
            }
    } else {
        // wo: fp32 out
#pragma unroll
        for (int mt = 0; mt < 4; mt++)
#pragma unroll
            for (int nt = 0; nt < 8; nt++) {
                int r0 = erow + mt * 16;
                int cc = ecol + (nt >> 1) * 16 + (nt & 1) * 8;
                *(float2*)&Cout[(size_t)r0 * D_ + cc]       = make_float2(c[mt][nt][0], c[mt][nt][1]);
                *(float2*)&Cout[(size_t)(r0 + 8) * D_ + cc] = make_float2(c[mt][nt][2], c[mt][nt][3]);
            }
    }
}

// ---------------------------------------------------------------------------
// Flash attention, all fp16: S = (Qh+Ql) x K (2 passes), PV = (Ph+Pl) x V.
// KV stage: K16h, V16 (2 arrays). exp2 softmax.
// Epilogue writes fp16 hi/lo attn-out (token-major) for the wo GEMM.
// ---------------------------------------------------------------------------
#define FROWB   144u
#define FQ_SIZE (128 * 144)
#define FKV_OFF (2 * FQ_SIZE)
#define FKV_ARR (128 * 144)
#define FSTAGE  (2 * FKV_ARR)              // 36864
#define FMMA_SMEM (FKV_OFF + 2 * FSTAGE)   // 110592

__device__ __forceinline__ void f_load_kv(
    uint32_t dst, const __half* kh, const __half* vh, size_t goff, int tid)
{
    int seg = tid & 7, r0 = tid >> 3;
    const __half* s0 = kh + goff + seg * 8;
    const __half* s1 = vh + goff + seg * 8;
    uint32_t d = dst + seg * 16;
#pragma unroll
    for (int rr = 0; rr < 4; rr++) {
        int row = r0 + rr * 32;
        cp_async16(d + row * FROWB, s0 + row * HD_);
        cp_async16(d + FKV_ARR + row * FROWB, s1 + row * HD_);
    }
}

__global__ __launch_bounds__(256, 1) void flash_mma_kernel(
    __half* __restrict__ Ohi, __half* __restrict__ Olo)
{
    extern __shared__ __align__(128) char fsm[];
    uint32_t sb = smem_to_u32(fsm);
    const int tid = threadIdx.x, wid = tid >> 5, lane = tid & 31;
    const int bh = blockIdx.x;
    const int qt = 15 - blockIdx.y;
    const int b = bh >> 4, h = bh & 15;
    const size_t headoff = (size_t)bh * T_ * HD_;
    const int nkt = qt + 1;

    {
        int seg = tid & 7, r0 = tid >> 3;
        const __half* q0 = g_q16h + headoff + (size_t)qt * 128 * HD_ + seg * 8;
        const __half* q1 = g_q16l + headoff + (size_t)qt * 128 * HD_ + seg * 8;
#pragma unroll
        for (int rr = 0; rr < 4; rr++) {
            int row = r0 + rr * 32;
            cp_async16(sb + row * FROWB + seg * 16, q0 + row * HD_);
            cp_async16(sb + FQ_SIZE + row * FROWB + seg * 16, q1 + row * HD_);
        }
    }
    f_load_kv(sb + FKV_OFF, g_k16h, g_v16, headoff, tid);
    cp_commit();

    uint32_t fqh[4][4], fql[4][4];
    float o[8][4];
#pragma unroll
    for (int nt = 0; nt < 8; nt++)
#pragma unroll
        for (int r = 0; r < 4; r++) o[nt][r] = 0.0f;
    float m0 = -1e30f, m1 = -1e30f, l0 = 0.0f, l1 = 0.0f;

    const uint32_t qrow_off = (uint32_t)(wid * 16 + (lane & 15)) * FROWB + (lane >> 4) * 16;
    const uint32_t krow_off = (uint32_t)((lane & 7) + ((lane >> 4) << 3)) * FROWB
                              + ((lane >> 3) & 1) * 16;
    const uint32_t vrow_off = (uint32_t)(lane & 15) * FROWB + (lane >> 4) * 16;

    for (int jt = 0; jt < nkt; jt++) {
        if (jt + 1 < nkt) {
            f_load_kv(sb + FKV_OFF + ((jt + 1) & 1) * FSTAGE, g_k16h, g_v16,
                      headoff + (size_t)(jt + 1) * 128 * HD_, tid);
            cp_commit();
            cp_wait<1>();
        } else {
            cp_wait<0>();
        }
        __syncthreads();

        if (jt == 0) {
#pragma unroll
            for (int ks = 0; ks < 4; ks++) {
                ldsm_x4(fqh[ks], sb + qrow_off + ks * 32);
                ldsm_x4(fql[ks], sb + FQ_SIZE + qrow_off + ks * 32);
            }
        }

        uint32_t st = sb + FKV_OFF + (jt & 1) * FSTAGE;

        float s[16][4];
#pragma unroll
        for (int nt = 0; nt < 16; nt++)
#pragma unroll
            for (int r = 0; r < 4; r++) s[nt][r] = 0.0f;

#pragma unroll
        for (int np = 0; np < 8; np++) {
#pragma unroll
            for (int ks = 0; ks < 4; ks++) {
                uint32_t addr = st + krow_off + np * 16 * FROWB + ks * 32;
                uint32_t fk[4];
                ldsm_x4(fk, addr);
                mma_f16(s[2 * np],     fqh[ks], fk + 0);
                mma_f16(s[2 * np + 1], fqh[ks], fk + 2);
                mma_f16(s[2 * np],     fql[ks], fk + 0);
                mma_f16(s[2 * np + 1], fql[ks], fk + 2);
            }
        }

        if (jt == qt) {
            int grow = qt * 128 + wid * 16 + (lane >> 2);
            int gc0 = jt * 128 + (lane & 3) * 2;
#pragma unroll
            for (int nt = 0; nt < 16; nt++) {
                int cc = gc0 + nt * 8;
                if (cc > grow)          s[nt][0] = -1e30f;
                if (cc + 1 > grow)      s[nt][1] = -1e30f;
                if (cc > grow + 8)      s[nt][2] = -1e30f;
                if (cc + 1 > grow + 8)  s[nt][3] = -1e30f;
            }
        }

        float mx0 = -1e30f, mx1 = -1e30f;
#pragma unroll
        for (int nt = 0; nt < 16; nt++) {
            mx0 = fmaxf(mx0, fmaxf(s[nt][0], s[nt][1]));
            mx1 = fmaxf(mx1, fmaxf(s[nt][2], s[nt][3]));
        }
        mx0 = fmaxf(mx0, __shfl_xor_sync(0xffffffffu, mx0, 1));
        mx0 = fmaxf(mx0, __shfl_xor_sync(0xffffffffu, mx0, 2));
        mx1 = fmaxf(mx1, __shfl_xor_sync(0xffffffffu, mx1, 1));
        mx1 = fmaxf(mx1, __shfl_xor_sync(0xffffffffu, mx1, 2));
        float mn0 = fmaxf(m0, mx0), mn1 = fmaxf(m1, mx1);
        float al0 = exp2f(m0 - mn0), al1 = exp2f(m1 - mn1);
        float rs0 = 0.0f, rs1 = 0.0f;
#pragma unroll
        for (int nt = 0; nt < 16; nt++) {
            s[nt][0] = exp2f(s[nt][0] - mn0);
            s[nt][1] = exp2f(s[nt][1] - mn0);
            s[nt][2] = exp2f(s[nt][2] - mn1);
            s[nt][3] = exp2f(s[nt][3] - mn1);
            rs0 += s[nt][0] + s[nt][1];
            rs1 += s[nt][2] + s[nt][3];
        }
        rs0 += __shfl_xor_sync(0xffffffffu, rs0, 1);
        rs0 += __shfl_xor_sync(0xffffffffu, rs0, 2);
        rs1 += __shfl_xor_sync(0xffffffffu, rs1, 1);
        rs1 += __shfl_xor_sync(0xffffffffu, rs1, 2);
        l0 = l0 * al0 + rs0; m0 = mn0;
        l1 = l1 * al1 + rs1; m1 = mn1;
#pragma unroll
        for (int nt = 0; nt < 8; nt++) {
            o[nt][0] *= al0; o[nt][1] *= al0;
            o[nt][2] *= al1; o[nt][3] *= al1;
        }

        // P -> fp16 hi/lo A-fragments
        uint32_t fph[8][4], fpl[8][4];
#pragma unroll
        for (int f = 0; f < 8; f++) {
#pragma unroll
            for (int half = 0; half < 2; half++) {
                int nt = 2 * f + half;
#pragma unroll
                for (int rh = 0; rh < 2; rh++) {
                    float p0 = s[nt][rh * 2], p1 = s[nt][rh * 2 + 1];
                    __half h0 = __float2half_rn(p0), h1 = __float2half_rn(p1);
                    fph[f][half * 2 + rh] = pack_half2(h0, h1);
                    fpl[f][half * 2 + rh] = pack_half2(
                        __float2half_rn(p0 - __half2float(h0)),
                        __float2half_rn(p1 - __half2float(h1)));
                }
            }
        }

        // O += P V (fp16 2-pass)
#pragma unroll
        for (int nh = 0; nh < 4; nh++) {
#pragma unroll
            for (int ks = 0; ks < 8; ks++) {
                uint32_t addr = st + FKV_ARR + vrow_off + ks * 16 * FROWB + nh * 32;
                uint32_t fv[4];
                ldsm_x4_t(fv, addr);
                mma_f16(o[2 * nh],     fph[ks], fv + 0);
                mma_f16(o[2 * nh + 1], fph[ks], fv + 2);
                mma_f16(o[2 * nh],     fpl[ks], fv + 0);
                mma_f16(o[2 * nh + 1], fpl[ks], fv + 2);
            }
        }
        __syncthreads();
    }

    // epilogue: normalize + fp16 hi/lo split, token-major [b][t][h*64+hd]
    float inv0 = 1.0f / l0, inv1 = 1.0f / l1;
    int row = qt * 128 + wid * 16 + (lane >> 2);
    size_t base0 = ((size_t)b * T_ + row) * D_ + h * 64 + (lane & 3) * 2;
    size_t base1 = base0 + (size_t)8 * D_;
#pragma unroll
    for (int nt = 0; nt < 8; nt++) {
        float v0 = o[nt][0] * inv0, v1 = o[nt][1] * inv0;
        float v2 = o[nt][2] * inv1, v3 = o[nt][3] * inv1;
        __half h0 = __float2half_rn(v0), h1 = __float2half_rn(v1);
        __half h2 = __float2half_rn(v2), h3 = __float2half_rn(v3);
        *reinterpret_cast<__half2*>(Ohi + base0 + nt * 8) = __halves2half2(h0, h1);
        *reinterpret_cast<__half2*>(Ohi + base1 + nt * 8) = __halves2half2(h2, h3);
        *reinterpret_cast<__half2*>(Olo + base0 + nt * 8) = __halves2half2(
            __float2half_rn(v0 - __half2float(h0)),
            __float2half_rn(v1 - __half2float(h1)));
        *reinterpret_cast<__half2*>(Olo + base1 + nt * 8) = __halves2half2(
            __float2half_rn(v2 - __half2float(h2)),
            __float2half_rn(v3 - __half2float(h3)));
    }
}

// ---------------------------------------------------------------------------
// Launch
// ---------------------------------------------------------------------------
extern "C" void kernel_launch(void* const* d_in, const int* in_sizes, int n_in,
                              void* d_out, int out_size)
{
    (void)in_sizes; (void)n_in; (void)out_size;
    const float* x  = (const float*)d_in[0];
    const float* w[4] = {(const float*)d_in[1], (const float*)d_in[2],
                         (const float*)d_in[3], (const float*)d_in[4]};
    float* out = (float*)d_out;

    __half *axh, *axl, *w16;
    cudaGetSymbolAddress((void**)&axh, g_axh);
    cudaGetSymbolAddress((void**)&axl, g_axl);
    cudaGetSymbolAddress((void**)&w16, g_w16);

    cudaFuncSetAttribute(gemm_qk_kernel,
                         cudaFuncAttributeMaxDynamicSharedMemorySize, GF_SMEM);
    cudaFuncSetAttribute(gemm_f16_kernel,
                         cudaFuncAttributeMaxDynamicSharedMemorySize, GF_SMEM);
    cudaFuncSetAttribute(flash_mma_kernel,
                         cudaFuncAttributeMaxDynamicSharedMemorySize, FMMA_SMEM);

    rope_freq_kernel<<<1, 16>>>();
    rope_tables_kernel<<<(T_ * 32 + 255) / 256, 256>>>();

    split_x_kernel<<<(NTOK * D_ / 4 + 255) / 256, 256>>>(x);
    split_w_kernel<<<(4 * D_ * D_ / 4 + 255) / 256, 256>>>(w[0], w[1], w[2], w[3]);

    // Q/K projections (fp16 2-pass, fused norm+rope epilogue -> fp16 hi/lo)
    gemm_qk_kernel<<<dim3(D_ / 128, NTOK / 256, 2), 256, GF_SMEM>>>(axh, axl);

    // V projection (fp16 2-pass) -> head-major fp16
    gemm_f16_kernel<<<dim3(D_ / 128, NTOK / 256, 1), 256, GF_SMEM>>>(
        axh, axl, w16 + 2 * (size_t)D_ * D_, 0, out);

    // flash: writes fp16 hi/lo attn-out into axh/axl
    flash_mma_kernel<<<dim3(BH_, T_ / 128), 256, FMMA_SMEM>>>(axh, axl);

    // wo projection (fp16 2-pass) -> fp32 out
    gemm_f16_kernel<<<dim3(D_ / 128, NTOK / 256, 1), 256, GF_SMEM>>>(
        axh, axl, w16 + 3 * (size_t)D_ * D_, 1, out);
}